// round 8
// baseline (speedup 1.0000x reference)
#include <cuda_runtime.h>
#include <cuda_fp16.h>

// Problem constants
#define Bz   2
#define Hh   160
#define Ww   160
#define SPAN 11
#define KK   23              // 2*SPAN+1
#define PH   (Hh + 2*SPAN)   // 182
#define PW   (Ww + 2*SPAN)   // 182
#define NPIX (Bz*Hh*Ww)      // 51200
#define HW   (Hh*Ww)

#define NBLK 148             // one persistent block per SM
#define NTHR 640             // 20 warps/SM (was 512); regs must be <=101

// s = sqrt(0.5*log2(e)); neighbor staged pre-scaled by 10*s, center by s,
// so d = s*(im_c - 10*im_p) and exp arg is simply -sum(d^2)   (ref's sigma bug)
#define SSC  0.8493218f
#define C1   (-0.72134752f)  // -0.5*log2(e), for spatial kernel

// __device__ globals: zero-initialized at load; pad regions never written;
// mutable state self-resets at the end of each launch (graph-replay safe).
__device__ uint4    g_pk[Bz*PH*PW];    // 8 halves: {10s*r,10s*g},{10s*b,src},{sy0,sy1},{sy2,0}
__device__ float4   g_crgb[NPIX];      // center rgb scaled by SSC ONLY (float, exact)
__device__ float4   g_cw[NPIX];        // center softmax {y0,y1,y2,0} (float)
__device__ int      g_list[NPIX];      // compacted active-pixel indices
__device__ int      g_count;
__device__ unsigned g_bar1;            // grid barrier (prep -> window)
__device__ unsigned g_unit;            // dynamic work counter (window phase)
__device__ unsigned g_done;            // completion ticket (fin phase)
__device__ double   g_ce;
__device__ double   g_gcrf;

__device__ __forceinline__ float ex2f(float x) {
    float y;
    asm("ex2.approx.f32 %0, %1;" : "=f"(y) : "f"(x));
    return y;
}

__device__ __forceinline__ unsigned h2u(__half2 h) {
    return *reinterpret_cast<unsigned*>(&h);
}

__global__ void __launch_bounds__(NTHR, 1) fused_kernel(
    const float* __restrict__ logit, const int* __restrict__ target,
    const float* __restrict__ image, const float* __restrict__ srcmap,
    const float* __restrict__ dstmap, float* __restrict__ out)
{
    __shared__ float red[NTHR/32];
    __shared__ float ftab[KK*Hh];      // spatial kernel f(d, pos), d-major: 14.7KB
    const int tid  = threadIdx.x;
    const int lane = tid & 31;
    const int wid  = tid >> 5;

    // ---------------- Phase 1: softmax, CE, staging, compaction -------------
    {
        int t = blockIdx.x * NTHR + tid;            // NBLK*NTHR=94720 >= NPIX
        float ce = 0.f;
        bool active = false;

        if (t < NPIX) {
            int b  = t / HW;
            int hw = t - b * HW;
            int i  = hw / Ww;
            int j  = hw - i * Ww;

            const float* lg = logit + (size_t)b * 3 * HW + hw;
            float l0 = lg[0], l1 = lg[HW], l2 = lg[2*HW];
            float m  = fmaxf(l0, fmaxf(l1, l2));
            float e0 = expf(l0 - m), e1 = expf(l1 - m), e2 = expf(l2 - m);
            float s  = e0 + e1 + e2;
            float inv = 1.f / s;
            float y0 = e0*inv, y1 = e1*inv, y2 = e2*inv;

            int   tg  = target[t];
            float lt  = (tg == 0) ? l0 : ((tg == 1) ? l1 : l2);
            float dst = dstmap[t];
            ce = -((lt - m) - logf(s)) * dst;

            const float* im = image + (size_t)b * 3 * HW + hw;
            float src = srcmap[t];
            // neighbor copy: scaled by 10*SSC (the /SIG_RGB=×10 from the ref bug)
            float sr = 10.f*SSC*im[0], sg = 10.f*SSC*im[HW], sb = 10.f*SSC*im[2*HW];

            int pidx = (b * PH + i + SPAN) * PW + (j + SPAN);
            uint4 pk;
            pk.x = h2u(__floats2half2_rn(sr, sg));
            pk.y = h2u(__floats2half2_rn(sb, src));
            pk.z = h2u(__floats2half2_rn(src*y0, src*y1));
            pk.w = h2u(__floats2half2_rn(src*y2, 0.f));
            g_pk[pidx]  = pk;
            // center copy: scaled by SSC ONLY (no ×10)
            g_crgb[t]   = make_float4(SSC*im[0], SSC*im[HW], SSC*im[2*HW], 0.f);
            g_cw[t]     = make_float4(y0, y1, y2, 0.f);

            active = (dst == 0.0f);                 // m_dst = 1 - dst
        }

        // fill spatial-kernel table while stores are in flight
        for (int idx = tid; idx < KK*Hh; idx += NTHR) {
            int d = idx / Hh;
            int pos = idx - d * Hh;
            float x = (float)(5*pos - d + SPAN) * (1.f/6.f);
            ftab[idx] = ex2f(x*x*C1);
        }

        // warp-aggregated compaction (NPIX % 32 == 0 -> warps are uniform)
        unsigned mask = __ballot_sync(0xffffffffu, active);
        if (mask) {
            int leader = __ffs(mask) - 1;
            int base   = 0;
            if (lane == leader) base = atomicAdd(&g_count, __popc(mask));
            base = __shfl_sync(0xffffffffu, base, leader);
            if (active) g_list[base + __popc(mask & ((1u << lane) - 1))] = t;
        }

        // block-reduce CE
        #pragma unroll
        for (int s2 = 16; s2 > 0; s2 >>= 1)
            ce += __shfl_xor_sync(0xffffffffu, ce, s2);
        if (lane == 0) red[wid] = ce;
        __syncthreads();
        if (wid == 0) {
            float v = (lane < NTHR/32) ? red[lane] : 0.f;
            #pragma unroll
            for (int s2 = 16; s2 > 0; s2 >>= 1)
                v += __shfl_xor_sync(0xffffffffu, v, s2);
            if (lane == 0) atomicAdd(&g_ce, (double)v);
        }
    }

    // ---------------- Grid barrier ------------------------------------------
    __syncthreads();
    if (tid == 0) {
        __threadfence();
        atomicAdd(&g_bar1, 1u);
        while (*(volatile unsigned*)&g_bar1 < NBLK) { __nanosleep(32); }
        __threadfence();
    }
    __syncthreads();

    // ---------------- Phase 2: window loop (dynamic half-window units) ------
    {
        const int count  = *(volatile int*)&g_count;
        const int nunits = ((count + 31) >> 5) * 2;  // 2 half-windows per chunk
        float acc = 0.f;

        for (;;) {
            int u = 0;
            if (lane == 0) u = (int)atomicAdd(&g_unit, 1u);
            u = __shfl_sync(0xffffffffu, u, 0);
            if (u >= nunits) break;

            int chunk = u >> 1;
            int half  = u & 1;
            int p     = (chunk << 5) + lane;
            if (p < count) {
                int t  = g_list[p];
                int b  = t / HW;
                int hw = t - b * HW;
                int i  = hw / Ww;
                int j  = hw - i * Ww;
                int base = (b * PH + i) * PW + j;    // padded window corner

                float4 cr = g_crgb[t];
                float c0 = cr.x, c1 = cr.y, c2 = cr.z;   // SSC-scaled center rgb
                float4 cy = g_cw[t];
                float y0p = cy.x, y1p = cy.y, y2p = cy.z;

                float fj[KK];
                #pragma unroll
                for (int d = 0; d < KK; d++)
                    fj[d] = ftab[d*Hh + j];              // smem table, no MUFU

                int dlo = half ? 12 : 0;
                int dhi = half ? KK : 12;
                #pragma unroll 1
                for (int di = dlo; di < dhi; di++) {
                    float fi = ftab[di*Hh + i];          // near-broadcast LDS
                    const uint4* ppk = g_pk + base + di*PW;
                    #pragma unroll
                    for (int dj = 0; dj < KK; dj++) {
                        uint4 v = __ldg(ppk + dj);
                        float2 rg  = __half22float2(*reinterpret_cast<const __half2*>(&v.x));
                        float2 bs  = __half22float2(*reinterpret_cast<const __half2*>(&v.y));
                        float2 y01 = __half22float2(*reinterpret_cast<const __half2*>(&v.z));
                        float2 y2_ = __half22float2(*reinterpret_cast<const __half2*>(&v.w));
                        float d0 = c0 - rg.x, d1 = c1 - rg.y, d2 = c2 - bs.x;
                        float ssn = d0 * (-d0);
                        ssn = fmaf(d1, -d1, ssn);
                        ssn = fmaf(d2, -d2, ssn);
                        float krgb = ex2f(ssn);              // exp(-0.5*||d||^2)
                        // sum_c src*y_qc*(1-y_pc) = src - (src*y_q).y_p
                        float sn = fmaf(y01.x, -y0p, bs.y);
                        sn = fmaf(y01.y, -y1p, sn);
                        sn = fmaf(y2_.x, -y2p, sn);
                        float km = fmaf(fi, fj[dj], krgb);   // k_rgb + k_xy
                        acc = fmaf(km, sn, acc);
                    }
                }
            }
        }

        // block-reduce gcrf partial
        #pragma unroll
        for (int s2 = 16; s2 > 0; s2 >>= 1)
            acc += __shfl_xor_sync(0xffffffffu, acc, s2);
        __syncthreads();                      // red[] reuse after phase 1
        if (lane == 0) red[wid] = acc;
        __syncthreads();
        if (wid == 0) {
            float v = (lane < NTHR/32) ? red[lane] : 0.f;
            #pragma unroll
            for (int s2 = 16; s2 > 0; s2 >>= 1)
                v += __shfl_xor_sync(0xffffffffu, v, s2);
            if (lane == 0) atomicAdd(&g_gcrf, (double)v);
        }
    }

    // ---------------- Fin: last block writes output + resets state ----------
    __syncthreads();
    if (tid == 0) {
        __threadfence();
        unsigned d = atomicAdd(&g_done, 1u);
        if (d == NBLK - 1) {                  // everyone's atomics are visible
            __threadfence();
            out[0] = (float)((g_ce + 0.15 * g_gcrf) / (double)NPIX);
            g_ce = 0.0; g_gcrf = 0.0;
            g_count = 0; g_bar1 = 0; g_unit = 0; g_done = 0;
        }
    }
}

extern "C" void kernel_launch(void* const* d_in, const int* in_sizes, int n_in,
                              void* d_out, int out_size)
{
    const float* logit  = (const float*)d_in[0];
    const int*   target = (const int*)  d_in[1];
    const float* image  = (const float*)d_in[2];
    const float* srcmap = (const float*)d_in[3];
    const float* dstmap = (const float*)d_in[4];
    float* out = (float*)d_out;

    fused_kernel<<<NBLK, NTHR>>>(logit, target, image, srcmap, dstmap, out);
}

// round 9
// speedup vs baseline: 1.2583x; 1.2583x over previous
#include <cuda_runtime.h>
#include <cuda_fp16.h>

// Problem constants
#define Bz   2
#define Hh   160
#define Ww   160
#define SPAN 11
#define KK   23              // 2*SPAN+1
#define PH   (Hh + 2*SPAN)   // 182
#define PW   (Ww + 2*SPAN)   // 182
#define NPIX (Bz*Hh*Ww)      // 51200
#define HW   (Hh*Ww)

#define NBLK 148             // one persistent block per SM
#define NTHR 512
#define NWARPS (NBLK*(NTHR/32))   // 2368 global warps

// s = sqrt(0.5*log2(e)); neighbor staged pre-scaled by 10*s, center by s,
// so d = s*(im_c - 10*im_p) and exp arg is simply -sum(d^2)   (ref's sigma bug)
#define SSC  0.8493218f
#define C1   (-0.72134752f)  // -0.5*log2(e), for spatial kernel

// __device__ globals: zero-initialized at load; pad regions never written;
// mutable state self-resets at the end of each launch (graph-replay safe).
__device__ uint4    g_pk[Bz*PH*PW];    // 8 halves: {10s*r,10s*g},{10s*b,src},{sy0,sy1},{sy2,0}
__device__ float4   g_crgb[NPIX];      // center rgb scaled by SSC ONLY (float, exact)
__device__ float4   g_cw[NPIX];        // center softmax {y0,y1,y2,0} (float)
__device__ int      g_list[NPIX];      // compacted active-pixel indices
__device__ int      g_count;
__device__ unsigned g_bar1;            // grid barrier (prep -> window)
__device__ unsigned g_done;            // completion ticket (fin phase)
__device__ double   g_ce;
__device__ double   g_gcrf;

__device__ __forceinline__ float ex2f(float x) {
    float y;
    asm("ex2.approx.f32 %0, %1;" : "=f"(y) : "f"(x));
    return y;
}

__device__ __forceinline__ unsigned h2u(__half2 h) {
    return *reinterpret_cast<unsigned*>(&h);
}

__global__ void __launch_bounds__(NTHR, 1) fused_kernel(
    const float* __restrict__ logit, const int* __restrict__ target,
    const float* __restrict__ image, const float* __restrict__ srcmap,
    const float* __restrict__ dstmap, float* __restrict__ out)
{
    __shared__ float red[NTHR/32];
    const int tid  = threadIdx.x;
    const int lane = tid & 31;
    const int wid  = tid >> 5;

    // ---------------- Phase 1: softmax, CE, staging, compaction -------------
    {
        int t = blockIdx.x * NTHR + tid;            // NBLK*NTHR=75776 >= NPIX
        float ce = 0.f;
        bool active = false;

        if (t < NPIX) {
            int b  = t / HW;
            int hw = t - b * HW;
            int i  = hw / Ww;
            int j  = hw - i * Ww;

            const float* lg = logit + (size_t)b * 3 * HW + hw;
            float l0 = lg[0], l1 = lg[HW], l2 = lg[2*HW];
            float m  = fmaxf(l0, fmaxf(l1, l2));
            float e0 = expf(l0 - m), e1 = expf(l1 - m), e2 = expf(l2 - m);
            float s  = e0 + e1 + e2;
            float inv = 1.f / s;
            float y0 = e0*inv, y1 = e1*inv, y2 = e2*inv;

            int   tg  = target[t];
            float lt  = (tg == 0) ? l0 : ((tg == 1) ? l1 : l2);
            float dst = dstmap[t];
            ce = -((lt - m) - logf(s)) * dst;

            const float* im = image + (size_t)b * 3 * HW + hw;
            float src = srcmap[t];
            // neighbor copy: scaled by 10*SSC (the /SIG_RGB=×10 from the ref bug)
            float sr = 10.f*SSC*im[0], sg = 10.f*SSC*im[HW], sb = 10.f*SSC*im[2*HW];

            int pidx = (b * PH + i + SPAN) * PW + (j + SPAN);
            uint4 pk;
            pk.x = h2u(__floats2half2_rn(sr, sg));
            pk.y = h2u(__floats2half2_rn(sb, src));
            pk.z = h2u(__floats2half2_rn(src*y0, src*y1));
            pk.w = h2u(__floats2half2_rn(src*y2, 0.f));
            g_pk[pidx]  = pk;
            // center copy: scaled by SSC ONLY (no ×10)
            g_crgb[t]   = make_float4(SSC*im[0], SSC*im[HW], SSC*im[2*HW], 0.f);
            g_cw[t]     = make_float4(y0, y1, y2, 0.f);

            active = (dst == 0.0f);                 // m_dst = 1 - dst
        }

        // warp-aggregated compaction (NPIX % 32 == 0 -> warps are uniform)
        unsigned mask = __ballot_sync(0xffffffffu, active);
        if (mask) {
            int leader = __ffs(mask) - 1;
            int base   = 0;
            if (lane == leader) base = atomicAdd(&g_count, __popc(mask));
            base = __shfl_sync(0xffffffffu, base, leader);
            if (active) g_list[base + __popc(mask & ((1u << lane) - 1))] = t;
        }

        // block-reduce CE
        #pragma unroll
        for (int s2 = 16; s2 > 0; s2 >>= 1)
            ce += __shfl_xor_sync(0xffffffffu, ce, s2);
        if (lane == 0) red[wid] = ce;
        __syncthreads();
        if (wid == 0) {
            float v = (lane < NTHR/32) ? red[lane] : 0.f;
            #pragma unroll
            for (int s2 = 8; s2 > 0; s2 >>= 1)
                v += __shfl_xor_sync(0xffffffffu, v, s2);
            if (lane == 0) atomicAdd(&g_ce, (double)v);
        }
    }

    // ---------------- Grid barrier ------------------------------------------
    __syncthreads();
    if (tid == 0) {
        __threadfence();
        atomicAdd(&g_bar1, 1u);
        while (*(volatile unsigned*)&g_bar1 < NBLK) { __nanosleep(32); }
        __threadfence();
    }
    __syncthreads();

    // ---------- Phase 2: window loop (STATIC strided unit assignment) -------
    {
        const int count  = *(volatile int*)&g_count;
        const int nunits = ((count + 31) >> 5) * 2;  // 2 half-windows per chunk
        const int gw     = blockIdx.x * (NTHR/32) + wid;   // global warp id
        float acc = 0.f;

        for (int u = gw; u < nunits; u += NWARPS) {  // no atomics: one wave
            int chunk = u >> 1;
            int half  = u & 1;
            int p     = (chunk << 5) + lane;
            if (p < count) {
                int t  = g_list[p];
                int b  = t / HW;
                int hw = t - b * HW;
                int i  = hw / Ww;
                int j  = hw - i * Ww;
                int base = (b * PH + i) * PW + j;    // padded window corner

                float4 cr = g_crgb[t];
                float c0 = cr.x, c1 = cr.y, c2 = cr.z;   // SSC-scaled center rgb
                float4 cy = g_cw[t];
                float y0p = cy.x, y1p = cy.y, y2p = cy.z;

                float fj[KK];
                #pragma unroll
                for (int d = 0; d < KK; d++) {
                    float xj = (float)(5*j - d + SPAN) * (1.f/6.f);
                    fj[d] = ex2f(xj*xj*C1);
                }

                int dlo = half ? 12 : 0;
                int dhi = half ? KK : 12;
                #pragma unroll 1
                for (int di = dlo; di < dhi; di++) {
                    float xi = (float)(5*i - di + SPAN) * (1.f/6.f);
                    float fi = ex2f(xi*xi*C1);
                    const uint4* ppk = g_pk + base + di*PW;
                    #pragma unroll
                    for (int dj = 0; dj < KK; dj++) {
                        uint4 v = __ldg(ppk + dj);
                        float2 rg  = __half22float2(*reinterpret_cast<const __half2*>(&v.x));
                        float2 bs  = __half22float2(*reinterpret_cast<const __half2*>(&v.y));
                        float2 y01 = __half22float2(*reinterpret_cast<const __half2*>(&v.z));
                        float2 y2_ = __half22float2(*reinterpret_cast<const __half2*>(&v.w));
                        float d0 = c0 - rg.x, d1 = c1 - rg.y, d2 = c2 - bs.x;
                        float ssn = d0 * (-d0);
                        ssn = fmaf(d1, -d1, ssn);
                        ssn = fmaf(d2, -d2, ssn);
                        float krgb = ex2f(ssn);              // exp(-0.5*||d||^2)
                        // sum_c src*y_qc*(1-y_pc) = src - (src*y_q).y_p
                        float sn = fmaf(y01.x, -y0p, bs.y);
                        sn = fmaf(y01.y, -y1p, sn);
                        sn = fmaf(y2_.x, -y2p, sn);
                        float km = fmaf(fi, fj[dj], krgb);   // k_rgb + k_xy
                        acc = fmaf(km, sn, acc);
                    }
                }
            }
        }

        // block-reduce gcrf partial
        #pragma unroll
        for (int s2 = 16; s2 > 0; s2 >>= 1)
            acc += __shfl_xor_sync(0xffffffffu, acc, s2);
        __syncthreads();                      // red[] reuse after phase 1
        if (lane == 0) red[wid] = acc;
        __syncthreads();
        if (wid == 0) {
            float v = (lane < NTHR/32) ? red[lane] : 0.f;
            #pragma unroll
            for (int s2 = 8; s2 > 0; s2 >>= 1)
                v += __shfl_xor_sync(0xffffffffu, v, s2);
            if (lane == 0) atomicAdd(&g_gcrf, (double)v);
        }
    }

    // ---------------- Fin: last block writes output + resets state ----------
    __syncthreads();
    if (tid == 0) {
        __threadfence();
        unsigned d = atomicAdd(&g_done, 1u);
        if (d == NBLK - 1) {                  // everyone's atomics are visible
            __threadfence();
            out[0] = (float)((g_ce + 0.15 * g_gcrf) / (double)NPIX);
            g_ce = 0.0; g_gcrf = 0.0;
            g_count = 0; g_bar1 = 0; g_done = 0;
        }
    }
}

extern "C" void kernel_launch(void* const* d_in, const int* in_sizes, int n_in,
                              void* d_out, int out_size)
{
    const float* logit  = (const float*)d_in[0];
    const int*   target = (const int*)  d_in[1];
    const float* image  = (const float*)d_in[2];
    const float* srcmap = (const float*)d_in[3];
    const float* dstmap = (const float*)d_in[4];
    float* out = (float*)d_out;

    fused_kernel<<<NBLK, NTHR>>>(logit, target, image, srcmap, dstmap, out);
}

// round 10
// speedup vs baseline: 1.4324x; 1.1383x over previous
#include <cuda_runtime.h>
#include <cuda_fp16.h>

// Problem constants
#define Bz   2
#define Hh   160
#define Ww   160
#define SPAN 11
#define KK   23              // 2*SPAN+1
#define PH   (Hh + 2*SPAN)   // 182
#define PW   (Ww + 2*SPAN)   // 182
#define PPW  96              // pairs per padded row (padded from 91)
#define NPIX (Bz*Hh*Ww)      // 51200
#define HW   (Hh*Ww)

#define NBLK 148
#define NTHR 512
#define NWARPS (NBLK*(NTHR/32))   // 2368

// s = sqrt(0.5*log2(e)); neighbor scaled by 10*s, center by s -> exp2 arg = -ss
#define SSC  0.8493218f
#define C1   (-0.72134752f)  // -0.5*log2(e)

// pair-staging tasks: 2 parities x Bz x 160 rows x m in [5,85]
#define NTASK (2*Bz*Hh*81)   // 51840

// __device__ globals: zero-init at load; pad entries never written (stay 0 =>
// src=0, sy=0 => zero contribution); mutable state self-resets per launch.
__device__ uint4  g_P1[2*Bz*PH*PPW];  // {r2,g2,b2,src2} half2 x4 per pair
__device__ uint4  g_P2[2*Bz*PH*PPW];  // {sy0_2,sy1_2,sy2_2,0}
__device__ float4 g_crgb[NPIX];       // center rgb * SSC (fp32)
__device__ float4 g_cw[NPIX];         // center softmax {y0,y1,y2,0}
__device__ int    g_list[NPIX];
__device__ int    g_count;
__device__ unsigned g_bar1, g_done;
__device__ double g_ce, g_gcrf;

__device__ __forceinline__ float ex2f(float x) {
    float y; asm("ex2.approx.f32 %0, %1;" : "=f"(y) : "f"(x)); return y;
}
__device__ __forceinline__ unsigned h2u(__half2 h) { return *reinterpret_cast<unsigned*>(&h); }
__device__ __forceinline__ __half2 u2h(unsigned u) { return *reinterpret_cast<__half2*>(&u); }
__device__ __forceinline__ __half2 hex2(__half2 x) {
    unsigned xi = h2u(x), yo;
    asm("ex2.approx.f16x2 %0, %1;" : "=r"(yo) : "r"(xi));
    return u2h(yo);
}
__device__ __forceinline__ __half2 h2and(__half2 a, unsigned m) {
    unsigned u = h2u(a) & m; return u2h(u);
}

// softmax + channel values for one padded column (zeros if pad column)
__device__ __forceinline__ void loadcol(
    const float* __restrict__ logit, const float* __restrict__ image,
    const float* __restrict__ srcmap, int b, int prow, int pcol, float* v)
{
    if (pcol < SPAN || pcol >= SPAN + Ww) {
        #pragma unroll
        for (int k = 0; k < 7; k++) v[k] = 0.f;
        return;
    }
    int i  = prow - SPAN, jj = pcol - SPAN;
    int hw = i * Ww + jj;
    const float* lg = logit + (size_t)b * 3 * HW + hw;
    float l0 = lg[0], l1 = lg[HW], l2 = lg[2*HW];
    float m  = fmaxf(l0, fmaxf(l1, l2));
    float e0 = expf(l0 - m), e1 = expf(l1 - m), e2 = expf(l2 - m);
    float inv = 1.f / (e0 + e1 + e2);
    float src = srcmap[b * HW + hw];
    const float* im = image + (size_t)b * 3 * HW + hw;
    v[0] = 10.f*SSC*im[0]; v[1] = 10.f*SSC*im[HW]; v[2] = 10.f*SSC*im[2*HW];
    v[3] = src;
    v[4] = src * e0 * inv; v[5] = src * e1 * inv; v[6] = src * e2 * inv;
}

__global__ void __launch_bounds__(NTHR, 1) fused_kernel(
    const float* __restrict__ logit, const int* __restrict__ target,
    const float* __restrict__ image, const float* __restrict__ srcmap,
    const float* __restrict__ dstmap, float* __restrict__ out)
{
    __shared__ float    red[NTHR/32];
    __shared__ unsigned s_fi[NTHR/32][KK+1];  // half2 broadcast {fi,fi} per di
    __shared__ unsigned s_fj[NTHR/32][12];    // {fj(2q), fj(2q+1)} per q
    const int tid  = threadIdx.x;
    const int lane = tid & 31;
    const int wid  = tid >> 5;

    // ============ Phase 1a: per-pixel softmax, CE, centers, compaction ======
    {
        int t = blockIdx.x * NTHR + tid;
        float ce = 0.f;
        bool active = false;

        if (t < NPIX) {
            int b  = t / HW;
            int hw = t - b * HW;

            const float* lg = logit + (size_t)b * 3 * HW + hw;
            float l0 = lg[0], l1 = lg[HW], l2 = lg[2*HW];
            float m  = fmaxf(l0, fmaxf(l1, l2));
            float e0 = expf(l0 - m), e1 = expf(l1 - m), e2 = expf(l2 - m);
            float s  = e0 + e1 + e2;
            float inv = 1.f / s;

            int   tg  = target[t];
            float lt  = (tg == 0) ? l0 : ((tg == 1) ? l1 : l2);
            float dst = dstmap[t];
            ce = -((lt - m) - logf(s)) * dst;

            const float* im = image + (size_t)b * 3 * HW + hw;
            g_crgb[t] = make_float4(SSC*im[0], SSC*im[HW], SSC*im[2*HW], 0.f);
            g_cw[t]   = make_float4(e0*inv, e1*inv, e2*inv, 0.f);

            active = (dst == 0.0f);
        }

        unsigned mask = __ballot_sync(0xffffffffu, active);
        if (mask) {
            int leader = __ffs(mask) - 1;
            int base   = 0;
            if (lane == leader) base = atomicAdd(&g_count, __popc(mask));
            base = __shfl_sync(0xffffffffu, base, leader);
            if (active) g_list[base + __popc(mask & ((1u << lane) - 1))] = t;
        }

        #pragma unroll
        for (int s2 = 16; s2 > 0; s2 >>= 1)
            ce += __shfl_xor_sync(0xffffffffu, ce, s2);
        if (lane == 0) red[wid] = ce;
        __syncthreads();
        if (wid == 0) {
            float v = (lane < NTHR/32) ? red[lane] : 0.f;
            #pragma unroll
            for (int s2 = 8; s2 > 0; s2 >>= 1)
                v += __shfl_xor_sync(0xffffffffu, v, s2);
            if (lane == 0) atomicAdd(&g_ce, (double)v);
        }
    }

    // ============ Phase 1b: channel-paired staging (both parity copies) =====
    {
        int tt = blockIdx.x * NTHR + tid;
        if (tt < NTASK) {
            int m   = tt % 81 + 5;        // pair index 5..85
            int r2  = tt / 81;
            int row = r2 % Hh + SPAN;     // padded row 11..170
            int r3  = r2 / Hh;            // 0..3
            int b   = r3 & 1;
            int p   = r3 >> 1;            // parity copy
            int c0  = 2*m + p;            // padded cols (c0, c0+1)

            float A[7], B[7];
            loadcol(logit, image, srcmap, b, row, c0,     A);
            loadcol(logit, image, srcmap, b, row, c0 + 1, B);

            uint4 o1, o2;
            o1.x = h2u(__floats2half2_rn(A[0], B[0]));   // r pair
            o1.y = h2u(__floats2half2_rn(A[1], B[1]));   // g pair
            o1.z = h2u(__floats2half2_rn(A[2], B[2]));   // b pair
            o1.w = h2u(__floats2half2_rn(A[3], B[3]));   // src pair
            o2.x = h2u(__floats2half2_rn(A[4], B[4]));   // sy0 pair
            o2.y = h2u(__floats2half2_rn(A[5], B[5]));   // sy1 pair
            o2.z = h2u(__floats2half2_rn(A[6], B[6]));   // sy2 pair
            o2.w = 0u;
            int idx = ((p * Bz + b) * PH + row) * PPW + m;
            g_P1[idx] = o1;
            g_P2[idx] = o2;
        }
    }

    // ================= Grid barrier =========================================
    __syncthreads();
    if (tid == 0) {
        __threadfence();
        atomicAdd(&g_bar1, 1u);
        while (*(volatile unsigned*)&g_bar1 < NBLK) { __nanosleep(32); }
        __threadfence();
    }
    __syncthreads();

    // ========== Phase 2: warp-per-pixel, 2 offsets per lane, half2 math =====
    {
        const int count = *(volatile int*)&g_count;
        const int gw    = blockIdx.x * (NTHR/32) + wid;
        float facc = 0.f;

        for (int px = gw; px < count; px += NWARPS) {
            int t  = g_list[px];
            int b  = t / HW;
            int hw = t - b * HW;
            int i  = hw / Ww;
            int j  = hw - i * Ww;

            // spatial tables (warp-cooperative, fp32 MUFU then half)
            if (lane < KK) {
                float xi = (float)(5*i - lane + SPAN) * (1.f/6.f);
                s_fi[wid][lane] = h2u(__float2half2_rn(ex2f(xi*xi*C1)));
            }
            if (lane < 12) {
                int djA = 2*lane;
                float xa = (float)(5*j - djA     + SPAN) * (1.f/6.f);
                float xb = (float)(5*j - djA - 1 + SPAN) * (1.f/6.f);
                s_fj[wid][lane] = h2u(__floats2half2_rn(ex2f(xa*xa*C1), ex2f(xb*xb*C1)));
            }
            float4 cr = g_crgb[t];
            float4 cy = g_cw[t];
            __half2 crr = __float2half2_rn(cr.x);
            __half2 cgg = __float2half2_rn(cr.y);
            __half2 cbb = __float2half2_rn(cr.z);
            __half2 ny0 = __float2half2_rn(-cy.x);
            __half2 ny1 = __float2half2_rn(-cy.y);
            __half2 ny2 = __float2half2_rn(-cy.z);
            const uint4* B1 = g_P1 + (((j & 1) * Bz + b) * PH + i) * PPW + (j >> 1);
            const uint4* B2 = g_P2 + (((j & 1) * Bz + b) * PH + i) * PPW + (j >> 1);
            __syncwarp();

            __half2 acc2 = u2h(0u);
            #pragma unroll
            for (int it = 0; it < 9; it++) {
                int s = it*32 + lane;                 // pair-slot 0..287
                bool valid = (s < 276);               // 23 rows x 12 pairs
                int sc = valid ? s : 0;
                int di = (sc * 2731) >> 15;           // sc/12
                int q  = sc - di * 12;
                unsigned msk = valid ? ((q == 11) ? 0x0000FFFFu : 0xFFFFFFFFu) : 0u;
                int idx = di * PPW + q;
                uint4 v1 = __ldg(B1 + idx);
                uint4 v2 = __ldg(B2 + idx);
                __half2 dr = __hsub2(crr, u2h(v1.x));
                __half2 dg = __hsub2(cgg, u2h(v1.y));
                __half2 db = __hsub2(cbb, u2h(v1.z));
                __half2 ss = __hfma2(dr, dr, __hfma2(dg, dg, __hmul2(db, db)));
                __half2 krgb = hex2(__hneg2(ss));     // exp(-0.5*||d||^2), 2 offs
                __half2 km = __hfma2(u2h(s_fi[wid][di]), u2h(s_fj[wid][q]), krgb);
                km = h2and(km, msk);                  // kill phantom col / tail
                __half2 sn = u2h(v1.w);               // src pair
                sn = __hfma2(u2h(v2.x), ny0, sn);
                sn = __hfma2(u2h(v2.y), ny1, sn);
                sn = __hfma2(u2h(v2.z), ny2, sn);     // src - (src*yq).yp
                acc2 = __hfma2(km, sn, acc2);
            }
            float2 fa = __half22float2(acc2);
            facc += fa.x + fa.y;
            __syncwarp();                              // before table overwrite
        }

        #pragma unroll
        for (int s2 = 16; s2 > 0; s2 >>= 1)
            facc += __shfl_xor_sync(0xffffffffu, facc, s2);
        __syncthreads();
        if (lane == 0) red[wid] = facc;
        __syncthreads();
        if (wid == 0) {
            float v = (lane < NTHR/32) ? red[lane] : 0.f;
            #pragma unroll
            for (int s2 = 8; s2 > 0; s2 >>= 1)
                v += __shfl_xor_sync(0xffffffffu, v, s2);
            if (lane == 0) atomicAdd(&g_gcrf, (double)v);
        }
    }

    // ================= Fin: last block writes + resets ======================
    __syncthreads();
    if (tid == 0) {
        __threadfence();
        unsigned d = atomicAdd(&g_done, 1u);
        if (d == NBLK - 1) {
            __threadfence();
            out[0] = (float)((g_ce + 0.15 * g_gcrf) / (double)NPIX);
            g_ce = 0.0; g_gcrf = 0.0;
            g_count = 0; g_bar1 = 0; g_done = 0;
        }
    }
}

extern "C" void kernel_launch(void* const* d_in, const int* in_sizes, int n_in,
                              void* d_out, int out_size)
{
    const float* logit  = (const float*)d_in[0];
    const int*   target = (const int*)  d_in[1];
    const float* image  = (const float*)d_in[2];
    const float* srcmap = (const float*)d_in[3];
    const float* dstmap = (const float*)d_in[4];
    float* out = (float*)d_out;

    fused_kernel<<<NBLK, NTHR>>>(logit, target, image, srcmap, dstmap, out);
}